// round 12
// baseline (speedup 1.0000x reference)
#include <cuda_runtime.h>
#include <cstdint>

// out[o,i,h,w] = sum_k weights[o,i,k] * x[k,h,w]
// OUT_CH = IN_CH = 2048, x is 3x3x3, output is (2048,2048,3,3) fp32.
//
// Transposed-assignment direct-store kernel: thread t computes global output
// float4 #t (floats 4t..4t+3) and stores it with one perfectly coalesced
// STG.128. No smem staging, no block barriers after the x preload, no TMA
// waits. Weight triples straddled by the 4 floats are loaded per-thread
// (adjacent lanes share pairs -> L1 sector hits on L2-resident weights);
// x selected from a 27-word smem table (distinct banks + broadcast).

__global__ void __launch_bounds__(256) gf_layer_kernel(
    const float* __restrict__ x,
    const float* __restrict__ w,
    float4* __restrict__ out4,
    int npairs) {
    __shared__ float xs[27];
    const int tid = threadIdx.x;
    if (tid < 27) xs[tid] = x[tid];
    __syncthreads();

    const int q = blockIdx.x * 256 + tid;   // global float4 index
    const int f = q * 4;                     // first float element index
    const int pair = f / 9;                  // compiler -> magic multiply
    const int rem = f - pair * 9;            // 0..8

    // Pair A coefficients (always valid).
    const float* __restrict__ wp = w + (long long)pair * 3;
    const float a0 = wp[0];
    const float a1 = wp[1];
    const float a2 = wp[2];

    // Pair B needed only when the 4 floats cross into the next pair
    // (rem >= 6). Guard the tail pair against OOB.
    float b0 = 0.f, b1 = 0.f, b2 = 0.f;
    if (rem >= 6 && pair + 1 < npairs) {
        b0 = wp[3];
        b1 = wp[4];
        b2 = wp[5];
    }

    float r[4];
#pragma unroll
    for (int m = 0; m < 4; m++) {
        const int jj = rem + m;               // 0..11
        const bool inA = (jj < 9);
        const int j = inA ? jj : jj - 9;      // 0..8
        const float c0 = inA ? a0 : b0;
        const float c1 = inA ? a1 : b1;
        const float c2 = inA ? a2 : b2;
        r[m] = fmaf(c0, xs[j], fmaf(c1, xs[9 + j], c2 * xs[18 + j]));
    }

    out4[q] = make_float4(r[0], r[1], r[2], r[3]);
}

extern "C" void kernel_launch(void* const* d_in, const int* in_sizes, int n_in,
                              void* d_out, int out_size) {
    // Inputs: x (27 elems), weights (2048*2048*3). Identify x by element count.
    const float* x;
    const float* w;
    long long w_elems;
    if (in_sizes[0] == 27) {
        x = (const float*)d_in[0];
        w = (const float*)d_in[1];
        w_elems = in_sizes[1];
    } else {
        x = (const float*)d_in[1];
        w = (const float*)d_in[0];
        w_elems = in_sizes[0];
    }

    const int npairs = (int)(w_elems / 3);            // 4,194,304
    const long long total_floats = (long long)npairs * 9;  // 37,748,736
    const int nquads = (int)(total_floats / 4);       // 9,437,184 (exact)
    const int threads = 256;
    const int blocks = nquads / threads;              // 36,864 (exact)

    gf_layer_kernel<<<blocks, threads>>>(x, w, (float4*)d_out, npairs);
}

// round 13
// speedup vs baseline: 1.2223x; 1.2223x over previous
#include <cuda_runtime.h>
#include <cstdint>

// out[o,i,h,w] = sum_k weights[o,i,k] * x[k,h,w]
// OUT_CH = IN_CH = 2048, x is 3x3x3, output is (2048,2048,3,3) fp32.
//
// Dual-path drain experiment: 128-thread blocks, each thread computes 2
// (o,i) pairs (18 floats) and stages them in smem. Warps 0-1 drain their
// contiguous 2304B slices via 1D TMA bulk stores; warps 2-3 drain theirs via
// lane-coalesced float4 __stcs stores. Both store paths (TMA engine and
// LSU/L1) run concurrently to probe whether the ~60% DRAM plateau is a
// per-path service limit rather than the DRAM write ceiling.

__global__ void __launch_bounds__(128, 12) gf_layer_kernel(
    const float* __restrict__ x,
    const float* __restrict__ w,
    float* __restrict__ out) {
    __shared__ alignas(128) float sout[128 * 18];  // 9 KB staging tile
    __shared__ alignas(16) float xs[28];

    const int tid = threadIdx.x;
    if (tid < 27) xs[tid] = x[tid];
    __syncthreads();

    // First (o,i) pair handled by this thread (2 pairs per thread).
    const long long p = ((long long)blockIdx.x * 128 + tid) * 2;

    // 6 contiguous weights (2 pairs x 3 coeffs); 24B-aligned -> 3x float2
    // loads. w (50MB) stays L2-resident.
    const float2* __restrict__ w2 = reinterpret_cast<const float2*>(w + p * 3);
    const float2 wa = w2[0];
    const float2 wb = w2[1];
    const float2 wc = w2[2];
    const float wv[6] = {wa.x, wa.y, wb.x, wb.y, wc.x, wc.y};

    float o[18];
#pragma unroll
    for (int pp = 0; pp < 2; pp++) {
        const float c0 = wv[pp * 3 + 0];
        const float c1 = wv[pp * 3 + 1];
        const float c2 = wv[pp * 3 + 2];
#pragma unroll
        for (int j = 0; j < 9; j++) {
            o[pp * 9 + j] = fmaf(c0, xs[j], fmaf(c1, xs[9 + j], c2 * xs[18 + j]));
        }
    }

    // Stage to smem as float2: thread stride = 18 floats = 72B. Conflict-free
    // (banks (18*l) mod 32 distinct per 16-lane phase).
    float2* __restrict__ s2 = reinterpret_cast<float2*>(sout + tid * 18);
#pragma unroll
    for (int i = 0; i < 9; i++) {
        s2[i] = make_float2(o[2 * i], o[2 * i + 1]);
    }

    const int wid = tid >> 5;
    const int lid = tid & 31;
    __syncwarp();

    // Warp wid owns slice sout[wid*576 .. +576) = 2304 bytes, contiguous in
    // both smem and gmem.
    if (wid < 2) {
        // TMA path.
        if (lid == 0) {
            const float* ssrc = sout + wid * (32 * 18);
            uint32_t saddr;
            asm("{ .reg .u64 t; cvta.to.shared.u64 t, %1; cvt.u32.u64 %0, t; }"
                : "=r"(saddr) : "l"(ssrc));
            float* gdst =
                out + (long long)blockIdx.x * (128 * 18) + wid * (32 * 18);
            asm volatile("fence.proxy.async.shared::cta;" ::: "memory");
            asm volatile(
                "cp.async.bulk.global.shared::cta.bulk_group [%0], [%1], %2;"
                :: "l"(gdst), "r"(saddr), "r"(32 * 18 * 4) : "memory");
            asm volatile("cp.async.bulk.commit_group;" ::: "memory");
            asm volatile("cp.async.bulk.wait_group 0;" ::: "memory");
        }
    } else {
        // STG path: drain own 144 float4 with lane-coalesced streaming stores.
        const float4* __restrict__ sr =
            reinterpret_cast<const float4*>(sout + wid * (32 * 18));
        float4* __restrict__ gdst4 = reinterpret_cast<float4*>(
            out + (long long)blockIdx.x * (128 * 18) + wid * (32 * 18));
#pragma unroll
        for (int i = 0; i < 5; i++) {
            const int idx = i * 32 + lid;
            if (idx < 144) {
                __stcs(&gdst4[idx], sr[idx]);
            }
        }
    }
}

extern "C" void kernel_launch(void* const* d_in, const int* in_sizes, int n_in,
                              void* d_out, int out_size) {
    // Inputs: x (27 elems), weights (2048*2048*3). Identify x by element count.
    const float* x;
    const float* w;
    long long w_elems;
    if (in_sizes[0] == 27) {
        x = (const float*)d_in[0];
        w = (const float*)d_in[1];
        w_elems = in_sizes[1];
    } else {
        x = (const float*)d_in[1];
        w = (const float*)d_in[0];
        w_elems = in_sizes[0];
    }

    float* out = (float*)d_out;

    const long long total_pairs = w_elems / 3;   // (o,i) pairs = 4,194,304
    const long long pairs_per_block = 128 * 2;   // 256
    const int blocks = (int)(total_pairs / pairs_per_block);  // 16384, exact

    gf_layer_kernel<<<blocks, 128>>>(x, w, out);
}

// round 14
// speedup vs baseline: 1.2290x; 1.0054x over previous
#include <cuda_runtime.h>
#include <cstdint>

// out[o,i,h,w] = sum_k weights[o,i,k] * x[k,h,w]
// OUT_CH = IN_CH = 2048, x is 3x3x3, output is (2048,2048,3,3) fp32.
//
// At the empirical DRAM write ceiling (~4.8TB/s). This variant minimizes
// instruction overhead per byte: 256 threads x 4 pairs/thread (36 floats),
// float4 smem staging, per-warp TMA bulk store of 4608B (2x fewer TMA ops
// and 2x fewer block prologues per byte than the 2-pair variants).

__global__ void __launch_bounds__(256, 5) gf_layer_kernel(
    const float* __restrict__ x,
    const float* __restrict__ w,
    float* __restrict__ out) {
    __shared__ alignas(128) float sout[256 * 36];  // 36 KB staging tile
    __shared__ alignas(16) float xs[28];

    const int tid = threadIdx.x;
    if (tid < 27) xs[tid] = x[tid];
    __syncthreads();

    // First (o,i) pair handled by this thread (4 pairs per thread).
    const long long p = ((long long)blockIdx.x * 256 + tid) * 4;

    // 12 contiguous weights (4 pairs x 3 coeffs); byte offset p*12 is
    // 48B-aligned -> 3x float4 loads. w (50MB) stays L2-resident.
    const float4* __restrict__ w4 = reinterpret_cast<const float4*>(w + p * 3);
    const float4 wa = w4[0];
    const float4 wb = w4[1];
    const float4 wc = w4[2];
    const float wv[12] = {wa.x, wa.y, wa.z, wa.w,
                          wb.x, wb.y, wb.z, wb.w,
                          wc.x, wc.y, wc.z, wc.w};

    alignas(16) float o[36];
#pragma unroll
    for (int pp = 0; pp < 4; pp++) {
        const float c0 = wv[pp * 3 + 0];
        const float c1 = wv[pp * 3 + 1];
        const float c2 = wv[pp * 3 + 2];
#pragma unroll
        for (int j = 0; j < 9; j++) {
            o[pp * 9 + j] = fmaf(c0, xs[j], fmaf(c1, xs[9 + j], c2 * xs[18 + j]));
        }
    }

    // Stage to smem as float4: thread stride = 36 floats = 144B (16B-aligned
    // from the 128B-aligned base). STS.128 phase = 8 lanes; banks
    // (36*l mod 32) = {4l}, all distinct -> conflict-free.
    float4* __restrict__ s4 = reinterpret_cast<float4*>(sout + tid * 36);
    const float4* __restrict__ o4 = reinterpret_cast<const float4*>(o);
#pragma unroll
    for (int i = 0; i < 9; i++) {
        s4[i] = o4[i];
    }

    // Per-warp TMA drain: warp wid owns sout[wid*1152 .. +1152) = 4608 bytes,
    // contiguous in both smem and gmem.
    const int wid = tid >> 5;
    const int lid = tid & 31;
    __syncwarp();

    if (lid == 0) {
        const float* ssrc = sout + wid * (32 * 36);
        uint32_t saddr;
        asm("{ .reg .u64 t; cvta.to.shared.u64 t, %1; cvt.u32.u64 %0, t; }"
            : "=r"(saddr) : "l"(ssrc));
        float* gdst =
            out + (long long)blockIdx.x * (256 * 36) + wid * (32 * 36);
        asm volatile("fence.proxy.async.shared::cta;" ::: "memory");
        asm volatile(
            "cp.async.bulk.global.shared::cta.bulk_group [%0], [%1], %2;"
            :: "l"(gdst), "r"(saddr), "r"(32 * 36 * 4) : "memory");
        asm volatile("cp.async.bulk.commit_group;" ::: "memory");
        // Wait before this warp's smem slice may be torn down (block exit).
        asm volatile("cp.async.bulk.wait_group 0;" ::: "memory");
    }
}

extern "C" void kernel_launch(void* const* d_in, const int* in_sizes, int n_in,
                              void* d_out, int out_size) {
    // Inputs: x (27 elems), weights (2048*2048*3). Identify x by element count.
    const float* x;
    const float* w;
    long long w_elems;
    if (in_sizes[0] == 27) {
        x = (const float*)d_in[0];
        w = (const float*)d_in[1];
        w_elems = in_sizes[1];
    } else {
        x = (const float*)d_in[1];
        w = (const float*)d_in[0];
        w_elems = in_sizes[0];
    }

    float* out = (float*)d_out;

    const long long total_pairs = w_elems / 3;   // (o,i) pairs = 4,194,304
    const long long pairs_per_block = 256 * 4;   // 1024
    const int blocks = (int)(total_pairs / pairs_per_block);  // 4096, exact

    gf_layer_kernel<<<blocks, 256>>>(x, w, out);
}